// round 11
// baseline (speedup 1.0000x reference)
#include <cuda_runtime.h>
#include <cstdint>

#define NROWS 4096
#define TWO_N 8192
#define DDIM  64
#define BM 128
#define NTILES 64              // 8192 / 128
#define NPAIRS 2080            // 64*65/2 upper-triangular tile pairs
#define NPREP  257             // 256 convert blocks + 1 hist block
#define INV_T 20.0f
#define PRESCALE 5.3715827f    // sqrt(20 * log2(e)); dot of scaled = ex2 exponent

// sim smem layout
#define OFF_A    0             // 128x64 bf16 swizzled (16KB)
#define OFF_B    16384         // 16KB
#define OFF_LABR 32768         // 128 ints
#define OFF_LABC 33280         // 128 ints
#define SMEM_BYTES 33792

__device__ __align__(128) uint2 g_feat[TWO_N * 16];   // prescaled bf16, 128B rows
__device__ float g_pt[TWO_N];
__device__ float g_ps[TWO_N];
__device__ float g_pos[NROWS];
__device__ int   g_cnt[64];
__device__ unsigned g_prep_cnt;   // zero-init; reset by finalize block
__device__ unsigned g_done;       // zero-init; reset by finalize block

static __device__ __forceinline__ uint32_t smem_u32(const void* p) {
    uint32_t a;
    asm("{ .reg .u64 t; cvta.to.shared.u64 t, %1; cvt.u32.u64 %0, t; }" : "=r"(a) : "l"(p));
    return a;
}
static __device__ __forceinline__ float ex2f(float x) {
    float r; asm("ex2.approx.f32 %0, %1;" : "=f"(r) : "f"(x)); return r;
}
static __device__ __forceinline__ uint32_t bf16pack(float lo, float hi) {
    uint32_t r; asm("cvt.rn.bf16x2.f32 %0, %1, %2;" : "=r"(r) : "f"(hi), "f"(lo)); return r;
}
static __device__ __forceinline__ void cpa16(uint32_t dst, const void* src) {
    asm volatile("cp.async.ca.shared.global [%0], [%1], 16;" :: "r"(dst), "l"(src));
}
#define CP_COMMIT() asm volatile("cp.async.commit_group;" ::: "memory")
#define CP_WAIT0()  asm volatile("cp.async.wait_group 0;" ::: "memory")

#define LDSM4(r0, r1, r2, r3, addr) \
    asm volatile("ldmatrix.sync.aligned.m8n8.x4.shared.b16 {%0,%1,%2,%3}, [%4];" \
                 : "=r"(r0), "=r"(r1), "=r"(r2), "=r"(r3) : "r"(addr))

#define MMA16816(d, a, b0, b1) \
    asm volatile("mma.sync.aligned.m16n8k16.row.col.f32.bf16.bf16.f32 " \
                 "{%0,%1,%2,%3}, {%4,%5,%6,%7}, {%8,%9}, {%0,%1,%2,%3};" \
                 : "+f"((d)[0]), "+f"((d)[1]), "+f"((d)[2]), "+f"((d)[3]) \
                 : "r"((a)[0]), "r"((a)[1]), "r"((a)[2]), "r"((a)[3]), "r"(b0), "r"(b1))

__global__ void __launch_bounds__(256, 3)
fused_kernel(const float* __restrict__ f1, const float* __restrict__ f2,
             const int* __restrict__ label, float* __restrict__ out) {
    extern __shared__ __align__(1024) char smem[];
    const uint32_t sb = smem_u32(smem);
    const int tid  = threadIdx.x;
    const int lane = tid & 31;
    const int wid  = tid >> 5;
    const int warpM = wid >> 1;
    const int warpN = wid & 1;
    const int bid = blockIdx.x;

    // ---- inline prep (blocks 0..255 convert; block 256 hist) ----
    if (bid < 256) {
        int r = bid * 16 + (tid >> 4);       // global row 0..4095
        int q = tid & 15;                    // float4 slot
        float4 v1 = ((const float4*)(f1 + r * DDIM))[q];
        float4 v2 = ((const float4*)(f2 + r * DDIM))[q];
        g_feat[r * 16 + q] =
            make_uint2(bf16pack(v1.x * PRESCALE, v1.y * PRESCALE),
                       bf16pack(v1.z * PRESCALE, v1.w * PRESCALE));
        g_feat[(r + NROWS) * 16 + q] =
            make_uint2(bf16pack(v2.x * PRESCALE, v2.y * PRESCALE),
                       bf16pack(v2.z * PRESCALE, v2.w * PRESCALE));
        float d = v1.x * v2.x + v1.y * v2.y + v1.z * v2.z + v1.w * v2.w;
        d += __shfl_xor_sync(0xffffffffu, d, 1);
        d += __shfl_xor_sync(0xffffffffu, d, 2);
        d += __shfl_xor_sync(0xffffffffu, d, 4);
        d += __shfl_xor_sync(0xffffffffu, d, 8);
        if (q == 0) g_pos[r] = __expf(d * INV_T);
        if (tid < 32) { g_pt[bid * 32 + tid] = 0.f; g_ps[bid * 32 + tid] = 0.f; }
        __threadfence();
        __syncthreads();
        if (tid == 0) atomicAdd(&g_prep_cnt, 1u);
    } else if (bid == 256) {
        __shared__ int h[64];
        if (tid < 64) h[tid] = 0;
        __syncthreads();
        for (int i = tid; i < NROWS; i += 256) atomicAdd(&h[label[i] & 63], 1);
        __syncthreads();
        if (tid < 64) g_cnt[tid] = h[tid];
        __threadfence();
        __syncthreads();
        if (tid == 0) atomicAdd(&g_prep_cnt, 1u);
    }

    // ---- wait for all prep contributions (wave-1 co-residency: occ>=2) ----
    if (tid == 0) {
        unsigned v;
        do {
            asm volatile("ld.acquire.gpu.global.b32 %0, [%1];"
                         : "=r"(v) : "l"(&g_prep_cnt));
            if (v >= NPREP) break;
            asm volatile("nanosleep.u32 128;");
        } while (true);
    }
    __syncthreads();

    // map linear pair index -> (ti, tj), ti <= tj
    const int t = bid;
    int ti = (int)(64.5f - sqrtf(64.5f * 64.5f - 2.0f * (float)t));
    while (64 * ti - ti * (ti - 1) / 2 > t) ti--;
    while (64 * (ti + 1) - (ti + 1) * ti / 2 <= t) ti++;
    const int tj = ti + (t - (64 * ti - ti * (ti - 1) / 2));
    const int row0 = ti * BM;
    const int col0 = tj * BM;

    // prologue: A (block ti), B (block tj), label slices
    {
        const char* gb = (const char*)g_feat;
#pragma unroll
        for (int it = 0; it < 4; it++) {
            int s = it * 256 + tid;
            int r = s >> 3, c = s & 7;
            uint32_t sw = (uint32_t)((c * 16) ^ ((r & 7) << 4));
            cpa16(sb + OFF_A + r * 128 + sw, gb + (size_t)(row0 + r) * 128 + c * 16);
            cpa16(sb + OFF_B + r * 128 + sw, gb + (size_t)(col0 + r) * 128 + c * 16);
        }
        if (tid < 32) cpa16(sb + OFF_LABR + tid * 16, label + (ti & 31) * 128 + tid * 4);
        else if (tid < 64) cpa16(sb + OFF_LABC + (tid - 32) * 16,
                                 label + (tj & 31) * 128 + (tid - 32) * 4);
        CP_COMMIT();
    }

    int rowA[2];
#pragma unroll
    for (int mb = 0; mb < 2; mb++)
        rowA[mb] = warpM * 32 + mb * 16 + (lane & 7) + ((lane >> 3) & 1) * 8;
    const int kaA = (lane >> 4) * 16;
    const int kbB = ((lane >> 3) & 1) * 16;

    CP_WAIT0();
    __syncthreads();

    const int* labr = (const int*)(smem + OFF_LABR);
    const int* labc = (const int*)(smem + OFF_LABC);
    int labR[4];
#pragma unroll
    for (int mb = 0; mb < 2; mb++)
#pragma unroll
        for (int h = 0; h < 2; h++)
            labR[mb * 2 + h] = labr[warpM * 32 + mb * 16 + (lane >> 2) + h * 8];

    const bool offdiag = (ti != tj);
    float tot[4] = {0.f, 0.f, 0.f, 0.f};
    float smv[4] = {0.f, 0.f, 0.f, 0.f};

#pragma unroll
    for (int hh = 0; hh < 2; hh++) {
        const int nbase = warpN * 64 + hh * 32;

        float acc[2][4][4];
#pragma unroll
        for (int mb = 0; mb < 2; mb++)
#pragma unroll
            for (int nb = 0; nb < 4; nb++)
#pragma unroll
                for (int e = 0; e < 4; e++) acc[mb][nb][e] = 0.f;

#pragma unroll
        for (int kc = 0; kc < 4; kc++) {
            uint32_t a[2][4];
#pragma unroll
            for (int mb = 0; mb < 2; mb++) {
                uint32_t addr = sb + OFF_A + rowA[mb] * 128
                              + ((kc * 32 + kaA) ^ ((rowA[mb] & 7) << 4));
                LDSM4(a[mb][0], a[mb][1], a[mb][2], a[mb][3], addr);
            }
#pragma unroll
            for (int pr = 0; pr < 2; pr++) {
                int nn = nbase + pr * 16 + (lane & 7) + ((lane >> 4) & 1) * 8;
                uint32_t b0, b1, b2, b3;
                uint32_t addr = sb + OFF_B + nn * 128
                              + ((kc * 32 + kbB) ^ ((nn & 7) << 4));
                LDSM4(b0, b1, b2, b3, addr);
#pragma unroll
                for (int mb = 0; mb < 2; mb++) {
                    MMA16816(acc[mb][2 * pr],     a[mb], b0, b1);
                    MMA16816(acc[mb][2 * pr + 1], a[mb], b2, b3);
                }
            }
        }

        // epilogue for this half: exp + row sums + col sums (ti<tj)
#pragma unroll
        for (int nb = 0; nb < 4; nb++) {
            int2 lb2 = *(const int2*)(labc + nbase + nb * 8 + (lane & 3) * 2);
            float ct0 = 0.f, ct1 = 0.f, cs0 = 0.f, cs1 = 0.f;
#pragma unroll
            for (int mb = 0; mb < 2; mb++)
#pragma unroll
                for (int h = 0; h < 2; h++) {
                    float e0 = ex2f(acc[mb][nb][2 * h]);
                    float e1 = ex2f(acc[mb][nb][2 * h + 1]);
                    float m0 = (lb2.x == labR[mb * 2 + h]) ? e0 : 0.f;
                    float m1 = (lb2.y == labR[mb * 2 + h]) ? e1 : 0.f;
                    tot[mb * 2 + h] += e0 + e1;
                    smv[mb * 2 + h] += m0 + m1;
                    ct0 += e0; ct1 += e1;
                    cs0 += m0; cs1 += m1;
                }
            if (offdiag) {
#pragma unroll
                for (int o = 4; o <= 16; o <<= 1) {
                    ct0 += __shfl_xor_sync(0xffffffffu, ct0, o);
                    ct1 += __shfl_xor_sync(0xffffffffu, ct1, o);
                    cs0 += __shfl_xor_sync(0xffffffffu, cs0, o);
                    cs1 += __shfl_xor_sync(0xffffffffu, cs1, o);
                }
                if ((lane >> 2) == 0) {
                    int gc = col0 + nbase + nb * 8 + (lane & 3) * 2;
                    atomicAdd(&g_pt[gc],     ct0);
                    atomicAdd(&g_pt[gc + 1], ct1);
                    atomicAdd(&g_ps[gc],     cs0);
                    atomicAdd(&g_ps[gc + 1], cs1);
                }
            }
        }
    }

    // row path: quad reduce + atomic add
#pragma unroll
    for (int i = 0; i < 4; i++) {
        float tv = tot[i], sv = smv[i];
        tv += __shfl_xor_sync(0xffffffffu, tv, 1);
        tv += __shfl_xor_sync(0xffffffffu, tv, 2);
        sv += __shfl_xor_sync(0xffffffffu, sv, 1);
        sv += __shfl_xor_sync(0xffffffffu, sv, 2);
        if ((lane & 3) == 0) {
            int grow = row0 + warpM * 32 + (i >> 1) * 16 + (lane >> 2) + (i & 1) * 8;
            atomicAdd(&g_pt[grow], tv);
            atomicAdd(&g_ps[grow], sv);
        }
    }

    // ---- last-block finalize ----
    __threadfence();
    __syncthreads();
    __shared__ unsigned rank_sh;
    if (tid == 0) rank_sh = atomicAdd(&g_done, 1u);
    __syncthreads();
    if (rank_sh == NPAIRS - 1) {
        __threadfence();   // all other blocks' g_pt/g_ps atomics visible
        float val = 0.f;
        for (int k = 0; k < TWO_N / 256; k++) {
            int i = k * 256 + tid;
            int i0 = i & (NROWS - 1);
            float Ng = g_pt[i] - g_ps[i];
            float term = log1pf(Ng / g_pos[i0]);       // == -log(pos/(Ng+pos))
            val += term / (float)(2 * g_cnt[label[i0] & 63]);
        }
#pragma unroll
        for (int o = 16; o > 0; o >>= 1) val += __shfl_down_sync(0xffffffffu, val, o);
        __shared__ float ws[8];
        if (lane == 0) ws[wid] = val;
        __syncthreads();
        if (wid == 0) {
            val = (lane < 8) ? ws[lane] : 0.f;
#pragma unroll
            for (int o = 4; o > 0; o >>= 1) val += __shfl_down_sync(0xffffffffu, val, o);
            if (lane == 0) {
                out[0] = val;
                g_prep_cnt = 0u;   // reset for next graph replay
                g_done = 0u;
            }
        }
    }
}

extern "C" void kernel_launch(void* const* d_in, const int* in_sizes, int n_in,
                              void* d_out, int out_size) {
    (void)in_sizes; (void)n_in; (void)out_size;
    const float* f1    = (const float*)d_in[0];
    const float* f2    = (const float*)d_in[1];
    const int*   label = (const int*)d_in[2];
    float*       out   = (float*)d_out;

    cudaFuncSetAttribute(fused_kernel, cudaFuncAttributeMaxDynamicSharedMemorySize, SMEM_BYTES);
    fused_kernel<<<NPAIRS, 256, SMEM_BYTES>>>(f1, f2, label, out);
}

// round 12
// speedup vs baseline: 1.5871x; 1.5871x over previous
#include <cuda_runtime.h>
#include <cstdint>

#define NROWS 4096
#define TWO_N 8192
#define DDIM  64
#define BM 128
#define NTILES 64              // 8192 / 128
#define NPAIRS 2080            // 64*65/2 upper-triangular tile pairs
#define INV_T 20.0f
#define PRESCALE 5.3715827f    // sqrt(20 * log2(e)); dot of scaled = ex2 exponent

// sim smem layout
#define OFF_A    0             // 128x64 bf16 swizzled (16KB)
#define OFF_B    16384         // 16KB
#define OFF_LABR 32768         // 128 ints
#define OFF_LABC 33280         // 128 ints
#define SMEM_BYTES 33792

__device__ __align__(128) uint2 g_feat[TWO_N * 16];   // prescaled bf16, 128B rows
__device__ float g_pt[TWO_N];
__device__ float g_ps[TWO_N];
__device__ float g_pos[NROWS];
__device__ int   g_cnt[64];

static __device__ __forceinline__ uint32_t smem_u32(const void* p) {
    uint32_t a;
    asm("{ .reg .u64 t; cvta.to.shared.u64 t, %1; cvt.u32.u64 %0, t; }" : "=r"(a) : "l"(p));
    return a;
}
static __device__ __forceinline__ float ex2f(float x) {
    float r; asm("ex2.approx.f32 %0, %1;" : "=f"(r) : "f"(x)); return r;
}
static __device__ __forceinline__ uint32_t bf16pack(float lo, float hi) {
    uint32_t r; asm("cvt.rn.bf16x2.f32 %0, %1, %2;" : "=r"(r) : "f"(hi), "f"(lo)); return r;
}
static __device__ __forceinline__ void cpa16(uint32_t dst, const void* src) {
    asm volatile("cp.async.cg.shared.global [%0], [%1], 16;" :: "r"(dst), "l"(src));
}
#define CP_COMMIT() asm volatile("cp.async.commit_group;" ::: "memory")
#define CP_WAIT0()  asm volatile("cp.async.wait_group 0;" ::: "memory")

#define LDSM4(r0, r1, r2, r3, addr) \
    asm volatile("ldmatrix.sync.aligned.m8n8.x4.shared.b16 {%0,%1,%2,%3}, [%4];" \
                 : "=r"(r0), "=r"(r1), "=r"(r2), "=r"(r3) : "r"(addr))

#define MMA16816(d, a, b0, b1) \
    asm volatile("mma.sync.aligned.m16n8k16.row.col.f32.bf16.bf16.f32 " \
                 "{%0,%1,%2,%3}, {%4,%5,%6,%7}, {%8,%9}, {%0,%1,%2,%3};" \
                 : "+f"((d)[0]), "+f"((d)[1]), "+f"((d)[2]), "+f"((d)[3]) \
                 : "r"((a)[0]), "r"((a)[1]), "r"((a)[2]), "r"((a)[3]), "r"(b0), "r"(b1))

// ---- prep: blocks 0..255 convert 16 rows each (one slot/thread), pos dots,
//      zero 32 accumulator entries; block 256: hist + out zero ----
__global__ void __launch_bounds__(256)
prep_kernel(const float* __restrict__ f1, const float* __restrict__ f2,
            const int* __restrict__ label, float* __restrict__ out) {
    const int tid = threadIdx.x;
    const int b = blockIdx.x;
    if (b < 256) {
        int r = b * 16 + (tid >> 4);         // global row 0..4095
        int q = tid & 15;                    // float4 slot
        float4 v1 = ((const float4*)(f1 + r * DDIM))[q];
        float4 v2 = ((const float4*)(f2 + r * DDIM))[q];
        g_feat[r * 16 + q] =
            make_uint2(bf16pack(v1.x * PRESCALE, v1.y * PRESCALE),
                       bf16pack(v1.z * PRESCALE, v1.w * PRESCALE));
        g_feat[(r + NROWS) * 16 + q] =
            make_uint2(bf16pack(v2.x * PRESCALE, v2.y * PRESCALE),
                       bf16pack(v2.z * PRESCALE, v2.w * PRESCALE));
        float d = v1.x * v2.x + v1.y * v2.y + v1.z * v2.z + v1.w * v2.w;
        d += __shfl_xor_sync(0xffffffffu, d, 1);
        d += __shfl_xor_sync(0xffffffffu, d, 2);
        d += __shfl_xor_sync(0xffffffffu, d, 4);
        d += __shfl_xor_sync(0xffffffffu, d, 8);
        if (q == 0) g_pos[r] = __expf(d * INV_T);
        if (tid < 32) { g_pt[b * 32 + tid] = 0.f; g_ps[b * 32 + tid] = 0.f; }
    } else {
        __shared__ int h[64];
        if (tid < 64) h[tid] = 0;
        __syncthreads();
        for (int i = tid; i < NROWS; i += 256) atomicAdd(&h[label[i] & 63], 1);
        __syncthreads();
        if (tid < 64) g_cnt[tid] = h[tid];
        if (tid == 0) out[0] = 0.f;
    }
}

// ---- sim: upper-triangular tile pairs; four 16-col strips per warp to cut
//      live accumulators (16 regs) and allow 4 CTAs/SM ----
__global__ void __launch_bounds__(256, 4)
sim_kernel(const int* __restrict__ label) {
    extern __shared__ __align__(1024) char smem[];
    const uint32_t sb = smem_u32(smem);
    const int tid  = threadIdx.x;
    const int lane = tid & 31;
    const int wid  = tid >> 5;
    const int warpM = wid >> 1;
    const int warpN = wid & 1;

    // map linear pair index -> (ti, tj), ti <= tj
    const int t = blockIdx.x;
    int ti = (int)(64.5f - sqrtf(64.5f * 64.5f - 2.0f * (float)t));
    while (64 * ti - ti * (ti - 1) / 2 > t) ti--;
    while (64 * (ti + 1) - (ti + 1) * ti / 2 <= t) ti++;
    const int tj = ti + (t - (64 * ti - ti * (ti - 1) / 2));
    const int row0 = ti * BM;
    const int col0 = tj * BM;

    // prologue: A (block ti), B (block tj), label slices
    {
        const char* gb = (const char*)g_feat;
#pragma unroll
        for (int it = 0; it < 4; it++) {
            int s = it * 256 + tid;
            int r = s >> 3, c = s & 7;
            uint32_t sw = (uint32_t)((c * 16) ^ ((r & 7) << 4));
            cpa16(sb + OFF_A + r * 128 + sw, gb + (size_t)(row0 + r) * 128 + c * 16);
            cpa16(sb + OFF_B + r * 128 + sw, gb + (size_t)(col0 + r) * 128 + c * 16);
        }
        if (tid < 32) cpa16(sb + OFF_LABR + tid * 16, label + (ti & 31) * 128 + tid * 4);
        else if (tid < 64) cpa16(sb + OFF_LABC + (tid - 32) * 16,
                                 label + (tj & 31) * 128 + (tid - 32) * 4);
        CP_COMMIT();
    }

    const int kaA = (lane >> 4) * 16;
    const int kbB = ((lane >> 3) & 1) * 16;

    CP_WAIT0();
    __syncthreads();

    const int* labr = (const int*)(smem + OFF_LABR);
    const int* labc = (const int*)(smem + OFF_LABC);
    int labR[4];
#pragma unroll
    for (int mb = 0; mb < 2; mb++)
#pragma unroll
        for (int h = 0; h < 2; h++)
            labR[mb * 2 + h] = labr[warpM * 32 + mb * 16 + (lane >> 2) + h * 8];

    const bool offdiag = (ti != tj);
    float tot[4] = {0.f, 0.f, 0.f, 0.f};
    float smv[4] = {0.f, 0.f, 0.f, 0.f};

#pragma unroll 1
    for (int qq = 0; qq < 4; qq++) {
        const int nbase = warpN * 64 + qq * 16;
        const int nn = nbase + (lane & 7) + ((lane >> 4) & 1) * 8;

        float acc[2][2][4];
#pragma unroll
        for (int mb = 0; mb < 2; mb++)
#pragma unroll
            for (int nb = 0; nb < 2; nb++)
#pragma unroll
                for (int e = 0; e < 4; e++) acc[mb][nb][e] = 0.f;

#pragma unroll
        for (int kc = 0; kc < 4; kc++) {
            uint32_t a[2][4];
#pragma unroll
            for (int mb = 0; mb < 2; mb++) {
                int rowA = warpM * 32 + mb * 16 + (lane & 7) + ((lane >> 3) & 1) * 8;
                uint32_t addr = sb + OFF_A + rowA * 128
                              + ((kc * 32 + kaA) ^ ((rowA & 7) << 4));
                LDSM4(a[mb][0], a[mb][1], a[mb][2], a[mb][3], addr);
            }
            uint32_t b0, b1, b2, b3;
            uint32_t addr = sb + OFF_B + nn * 128
                          + ((kc * 32 + kbB) ^ ((nn & 7) << 4));
            LDSM4(b0, b1, b2, b3, addr);
#pragma unroll
            for (int mb = 0; mb < 2; mb++) {
                MMA16816(acc[mb][0], a[mb], b0, b1);
                MMA16816(acc[mb][1], a[mb], b2, b3);
            }
        }

        // epilogue for this strip: exp + row sums + col sums (ti<tj)
#pragma unroll
        for (int nb = 0; nb < 2; nb++) {
            int2 lb2 = *(const int2*)(labc + nbase + nb * 8 + (lane & 3) * 2);
            float ct0 = 0.f, ct1 = 0.f, cs0 = 0.f, cs1 = 0.f;
#pragma unroll
            for (int mb = 0; mb < 2; mb++)
#pragma unroll
                for (int h = 0; h < 2; h++) {
                    float e0 = ex2f(acc[mb][nb][2 * h]);
                    float e1 = ex2f(acc[mb][nb][2 * h + 1]);
                    float m0 = (lb2.x == labR[mb * 2 + h]) ? e0 : 0.f;
                    float m1 = (lb2.y == labR[mb * 2 + h]) ? e1 : 0.f;
                    tot[mb * 2 + h] += e0 + e1;
                    smv[mb * 2 + h] += m0 + m1;
                    ct0 += e0; ct1 += e1;
                    cs0 += m0; cs1 += m1;
                }
            if (offdiag) {
#pragma unroll
                for (int o = 4; o <= 16; o <<= 1) {
                    ct0 += __shfl_xor_sync(0xffffffffu, ct0, o);
                    ct1 += __shfl_xor_sync(0xffffffffu, ct1, o);
                    cs0 += __shfl_xor_sync(0xffffffffu, cs0, o);
                    cs1 += __shfl_xor_sync(0xffffffffu, cs1, o);
                }
                if ((lane >> 2) == 0) {
                    int gc = col0 + nbase + nb * 8 + (lane & 3) * 2;
                    atomicAdd(&g_pt[gc],     ct0);
                    atomicAdd(&g_pt[gc + 1], ct1);
                    atomicAdd(&g_ps[gc],     cs0);
                    atomicAdd(&g_ps[gc + 1], cs1);
                }
            }
        }
    }

    // row path: quad reduce + atomic add
#pragma unroll
    for (int i = 0; i < 4; i++) {
        float tv = tot[i], sv = smv[i];
        tv += __shfl_xor_sync(0xffffffffu, tv, 1);
        tv += __shfl_xor_sync(0xffffffffu, tv, 2);
        sv += __shfl_xor_sync(0xffffffffu, sv, 1);
        sv += __shfl_xor_sync(0xffffffffu, sv, 2);
        if ((lane & 3) == 0) {
            int grow = row0 + warpM * 32 + (i >> 1) * 16 + (lane >> 2) + (i & 1) * 8;
            atomicAdd(&g_pt[grow], tv);
            atomicAdd(&g_ps[grow], sv);
        }
    }
}

__global__ void __launch_bounds__(128)
finalize_kernel(const int* __restrict__ label, float* __restrict__ out) {
    int i = blockIdx.x * blockDim.x + threadIdx.x;   // 64 x 128 = 8192
    int i0 = i & (NROWS - 1);
    float Ng   = g_pt[i] - g_ps[i];
    float term = log1pf(Ng / g_pos[i0]);      // == -log(pos/(Ng+pos))
    int   gs   = 2 * g_cnt[label[i0] & 63];
    float val  = term / (float)gs;
#pragma unroll
    for (int o = 16; o > 0; o >>= 1) val += __shfl_down_sync(0xffffffffu, val, o);
    __shared__ float ws[4];
    int lane = threadIdx.x & 31, w = threadIdx.x >> 5;
    if (lane == 0) ws[w] = val;
    __syncthreads();
    if (w == 0) {
        val = (lane < 4) ? ws[lane] : 0.f;
#pragma unroll
        for (int o = 2; o > 0; o >>= 1) val += __shfl_down_sync(0xffffffffu, val, o);
        if (lane == 0) atomicAdd(out, val);
    }
}

extern "C" void kernel_launch(void* const* d_in, const int* in_sizes, int n_in,
                              void* d_out, int out_size) {
    (void)in_sizes; (void)n_in; (void)out_size;
    const float* f1    = (const float*)d_in[0];
    const float* f2    = (const float*)d_in[1];
    const int*   label = (const int*)d_in[2];
    float*       out   = (float*)d_out;

    cudaFuncSetAttribute(sim_kernel, cudaFuncAttributeMaxDynamicSharedMemorySize, SMEM_BYTES);

    prep_kernel<<<257, 256>>>(f1, f2, label, out);
    sim_kernel<<<NPAIRS, 256, SMEM_BYTES>>>(label);
    finalize_kernel<<<64, 128>>>(label, out);
}